// round 1
// baseline (speedup 1.0000x reference)
#include <cuda_runtime.h>
#include <math.h>

// Problem constants
#define BB   4
#define CIN  128
#define HH   96
#define WWW  96
#define OO   128
#define PP   9216      // H*W
#define NTAP 9
#define PT   64        // pixel tile per block
#define NPT  144       // PP / PT

// Scratch for offset/mask conv results (device globals — no allocation allowed)
__device__ float g_off [BB * 18 * PP];   // (b, 2k+d, p)
__device__ float g_mask[BB * 9  * PP];   // (b, k, p) — sigmoid applied

// ---------------------------------------------------------------------------
// Kernel 1: offset conv (18ch) + mask conv (9ch, sigmoid), fused as one
// implicit GEMM:  Y[32ocslots, 64p] = W[32,1152] @ Im2col[1152,64]
// Block: 256 threads, thread tile 2oc x 4p.
// ---------------------------------------------------------------------------
__global__ __launch_bounds__(256) void offmask_kernel(
    const float* __restrict__ x2,
    const float* __restrict__ offset_w, const float* __restrict__ offset_b,
    const float* __restrict__ mask_w,   const float* __restrict__ mask_b)
{
    __shared__ __align__(16) float wsm[16][32];
    __shared__ __align__(16) float vsm[16][64];

    const int tid = threadIdx.x;
    const int b  = blockIdx.y;
    const int p0 = blockIdx.x * PT;
    const int tx = tid & 15;        // -> 4 pixels
    const int ty = tid >> 4;        // -> 2 out channels

    float acc[2][4];
#pragma unroll
    for (int i = 0; i < 2; i++)
#pragma unroll
        for (int j = 0; j < 4; j++) acc[i][j] = 0.f;

    for (int k = 0; k < 9; k++) {
        const int ky = k / 3, kx = k % 3;
        for (int cb = 0; cb < 8; cb++) {
            const int c0 = cb * 16;
            __syncthreads();
            // stage weights: [cc][oc]  (oc<18: offset, 18..26: mask, else 0)
#pragma unroll
            for (int r = 0; r < 2; r++) {
                int idx = tid + r * 256;
                int cc = idx >> 5, oc = idx & 31;
                float w = 0.f;
                if (oc < 18)      w = offset_w[(oc * CIN + c0 + cc) * 9 + k];
                else if (oc < 27) w = mask_w[((oc - 18) * CIN + c0 + cc) * 9 + k];
                wsm[cc][oc] = w;
            }
            // stage im2col values: [cc][pp]
#pragma unroll
            for (int r = 0; r < 4; r++) {
                int idx = tid + r * 256;
                int cc = idx >> 6, pl = idx & 63;
                int p  = p0 + pl;
                int ho = p / WWW, wo = p % WWW;
                int y = ho - 1 + ky, x = wo - 1 + kx;
                float v = 0.f;
                if ((unsigned)y < (unsigned)HH && (unsigned)x < (unsigned)WWW)
                    v = x2[((b * CIN + c0 + cc) * HH + y) * WWW + x];
                vsm[cc][pl] = v;
            }
            __syncthreads();
#pragma unroll
            for (int cc = 0; cc < 16; cc++) {
                float2 w = *(const float2*)&wsm[cc][ty * 2];
                float4 v = *(const float4*)&vsm[cc][tx * 4];
                acc[0][0] = fmaf(w.x, v.x, acc[0][0]);
                acc[0][1] = fmaf(w.x, v.y, acc[0][1]);
                acc[0][2] = fmaf(w.x, v.z, acc[0][2]);
                acc[0][3] = fmaf(w.x, v.w, acc[0][3]);
                acc[1][0] = fmaf(w.y, v.x, acc[1][0]);
                acc[1][1] = fmaf(w.y, v.y, acc[1][1]);
                acc[1][2] = fmaf(w.y, v.z, acc[1][2]);
                acc[1][3] = fmaf(w.y, v.w, acc[1][3]);
            }
        }
    }

    // epilogue: bias; sigmoid for mask channels
#pragma unroll
    for (int i = 0; i < 2; i++) {
        int oc = ty * 2 + i;
#pragma unroll
        for (int j = 0; j < 4; j++) {
            int p = p0 + tx * 4 + j;
            if (oc < 18) {
                g_off[(b * 18 + oc) * PP + p] = acc[i][j] + offset_b[oc];
            } else if (oc < 27) {
                float s = acc[i][j] + mask_b[oc - 18];
                g_mask[(b * 9 + (oc - 18)) * PP + p] = 1.f / (1.f + expf(-s));
            }
        }
    }
}

// ---------------------------------------------------------------------------
// Kernel 2: modulated deformable conv v2 as implicit GEMM:
//   out[128o, 64p] = W[128, 1152] @ V[1152, 64]
// where V[c*9+k, p] = sum_{4 corners} wt * x[b, c, idx]  (bilinear + mask).
// Corner indices/weights precomputed once per block into smem.
// Block: 256 threads, thread tile 8oc x 4p.
// ---------------------------------------------------------------------------
__global__ __launch_bounds__(256) void deform_kernel(
    const float* __restrict__ x,
    const float* __restrict__ deform_w, const float* __restrict__ deform_b,
    float* __restrict__ out)
{
    __shared__ __align__(16) int   sidx[9][64][4];
    __shared__ __align__(16) float swt [9][64][4];
    __shared__ __align__(16) float wsm[16][128];
    __shared__ __align__(16) float vsm[16][64];

    const int tid = threadIdx.x;
    const int b  = blockIdx.y;
    const int p0 = blockIdx.x * PT;
    const int tx = tid & 15;        // -> 4 pixels
    const int ty = tid >> 4;        // -> 8 out channels

    // ---- precompute bilinear corner metadata for 64 pixels x 9 taps ----
    for (int idx = tid; idx < 9 * 64; idx += 256) {
        int k = idx >> 6, pl = idx & 63;
        int p  = p0 + pl;
        int ho = p / WWW, wo = p % WWW;
        int ky = k / 3, kx = k % 3;
        float dy = g_off[(b * 18 + 2 * k    ) * PP + p];
        float dx = g_off[(b * 18 + 2 * k + 1) * PP + p];
        float m  = g_mask[(b * 9 + k) * PP + p];
        float py = (float)(ho - 1 + ky) + dy;
        float px = (float)(wo - 1 + kx) + dx;
        float fy = floorf(py), fx = floorf(px);
        int y0 = (int)fy, x0 = (int)fx;
        int y1 = y0 + 1,  x1 = x0 + 1;
        float ly = py - fy, lx = px - fx;
        float hy = 1.f - ly, hx = 1.f - lx;
        bool vy0 = (unsigned)y0 < (unsigned)HH, vy1 = (unsigned)y1 < (unsigned)HH;
        bool vx0 = (unsigned)x0 < (unsigned)WWW, vx1 = (unsigned)x1 < (unsigned)WWW;
        bool v00 = vy0 && vx0, v01 = vy0 && vx1, v10 = vy1 && vx0, v11 = vy1 && vx1;
        sidx[k][pl][0] = v00 ? (y0 * WWW + x0) : 0;
        sidx[k][pl][1] = v01 ? (y0 * WWW + x1) : 0;
        sidx[k][pl][2] = v10 ? (y1 * WWW + x0) : 0;
        sidx[k][pl][3] = v11 ? (y1 * WWW + x1) : 0;
        swt[k][pl][0] = v00 ? hy * hx * m : 0.f;
        swt[k][pl][1] = v01 ? hy * lx * m : 0.f;
        swt[k][pl][2] = v10 ? ly * hx * m : 0.f;
        swt[k][pl][3] = v11 ? ly * lx * m : 0.f;
    }
    __syncthreads();

    float acc[8][4];
#pragma unroll
    for (int i = 0; i < 8; i++)
#pragma unroll
        for (int j = 0; j < 4; j++) acc[i][j] = 0.f;

    for (int k = 0; k < 9; k++) {
        for (int cb = 0; cb < 8; cb++) {
            const int c0 = cb * 16;
            __syncthreads();
            // stage weights: [cc][oc]
#pragma unroll
            for (int r = 0; r < 8; r++) {
                int idx = tid + r * 256;
                int cc = idx >> 7, oc = idx & 127;
                wsm[cc][oc] = deform_w[(oc * CIN + c0 + cc) * 9 + k];
            }
            // stage sampled values: [cc][pp]
#pragma unroll
            for (int r = 0; r < 4; r++) {
                int idx = tid + r * 256;
                int cc = idx >> 6, pl = idx & 63;
                const float* base = x + (size_t)(b * CIN + c0 + cc) * PP;
                int4   id = *(const int4*)  &sidx[k][pl][0];
                float4 w  = *(const float4*)&swt [k][pl][0];
                float v = w.x * base[id.x];
                v = fmaf(w.y, base[id.y], v);
                v = fmaf(w.z, base[id.z], v);
                v = fmaf(w.w, base[id.w], v);
                vsm[cc][pl] = v;
            }
            __syncthreads();
            // 16-step rank-1 updates: 8oc x 4p per thread
#pragma unroll
            for (int cc = 0; cc < 16; cc++) {
                float4 wa = *(const float4*)&wsm[cc][ty * 8];
                float4 wb = *(const float4*)&wsm[cc][ty * 8 + 4];
                float4 v  = *(const float4*)&vsm[cc][tx * 4];
                float wv[8] = {wa.x, wa.y, wa.z, wa.w, wb.x, wb.y, wb.z, wb.w};
                float vv[4] = {v.x, v.y, v.z, v.w};
#pragma unroll
                for (int i = 0; i < 8; i++)
#pragma unroll
                    for (int j = 0; j < 4; j++)
                        acc[i][j] = fmaf(wv[i], vv[j], acc[i][j]);
            }
        }
    }

    // epilogue: bias + vectorized store
#pragma unroll
    for (int i = 0; i < 8; i++) {
        int oc = ty * 8 + i;
        float bias = deform_b[oc];
        float4 o;
        o.x = acc[i][0] + bias;
        o.y = acc[i][1] + bias;
        o.z = acc[i][2] + bias;
        o.w = acc[i][3] + bias;
        *(float4*)&out[(size_t)(b * OO + oc) * PP + p0 + tx * 4] = o;
    }
}

// ---------------------------------------------------------------------------
extern "C" void kernel_launch(void* const* d_in, const int* in_sizes, int n_in,
                              void* d_out, int out_size)
{
    const float* x        = (const float*)d_in[0];
    const float* x2       = (const float*)d_in[1];
    const float* offset_w = (const float*)d_in[2];
    const float* offset_b = (const float*)d_in[3];
    const float* mask_w   = (const float*)d_in[4];
    const float* mask_b   = (const float*)d_in[5];
    const float* deform_w = (const float*)d_in[6];
    const float* deform_b = (const float*)d_in[7];
    float* out = (float*)d_out;

    dim3 grid(NPT, BB);
    offmask_kernel<<<grid, 256>>>(x2, offset_w, offset_b, mask_w, mask_b);
    deform_kernel<<<grid, 256>>>(x, deform_w, deform_b, out);
}

// round 2
// speedup vs baseline: 1.9257x; 1.9257x over previous
#include <cuda_runtime.h>
#include <math.h>

// Problem constants
#define BB   4
#define CIN  128
#define HH   96
#define WWW  96
#define OO   128
#define PP   9216      // H*W
#define PT   64        // pixel tile per block
#define NPT  144       // PP / PT

// Scratch (device globals — no allocation allowed)
__device__ float g_off [BB * 18 * PP];        // (b, 2k+d, p)
__device__ float g_mask[BB * 9  * PP];        // (b, k, p) — sigmoid applied
__device__ float g_wt  [9 * CIN * OO];        // (k, c, o)  transposed deform_w
__device__ float g_owt [9 * CIN * 32];        // (k, c, slot) transposed offset/mask w

// ---------------------------------------------------------------------------
// Kernel 0: one-time weight transposes so GEMM staging is coalesced.
// ---------------------------------------------------------------------------
__global__ __launch_bounds__(256) void transpose_w_kernel(
    const float* __restrict__ dw,
    const float* __restrict__ ow,
    const float* __restrict__ mw)
{
    int i = blockIdx.x * 256 + threadIdx.x;
    if (i < 9 * CIN * OO) {
        int o = i & 127, c = (i >> 7) & 127, k = i >> 14;
        g_wt[i] = dw[(o * CIN + c) * 9 + k];
    }
    if (i < 9 * CIN * 32) {
        int s = i & 31, c = (i >> 5) & 127, k = i >> 12;
        float w = 0.f;
        if (s < 18)      w = ow[(s * CIN + c) * 9 + k];
        else if (s < 27) w = mw[((s - 18) * CIN + c) * 9 + k];
        g_owt[i] = w;
    }
}

// ---------------------------------------------------------------------------
// Kernel 1: offset conv (18ch) + mask conv (9ch, sigmoid), fused implicit GEMM
//   Y[32slots, 64p] = W[32,1152] @ Im2col[1152,64]
// Block: 256 threads, thread tile 2oc x 4p. Weights staged coalesced from g_owt.
// ---------------------------------------------------------------------------
__global__ __launch_bounds__(256) void offmask_kernel(
    const float* __restrict__ x2,
    const float* __restrict__ offset_b, const float* __restrict__ mask_b)
{
    __shared__ __align__(16) float wsm[16][32];
    __shared__ __align__(16) float vsm[16][64];

    const int tid = threadIdx.x;
    const int b  = blockIdx.y;
    const int p0 = blockIdx.x * PT;
    const int tx = tid & 15;        // -> 4 pixels
    const int ty = tid >> 4;        // -> 2 out channels

    float acc[2][4];
#pragma unroll
    for (int i = 0; i < 2; i++)
#pragma unroll
        for (int j = 0; j < 4; j++) acc[i][j] = 0.f;

    for (int k = 0; k < 9; k++) {
        const int ky = k / 3, kx = k % 3;
        for (int cb = 0; cb < 8; cb++) {
            const int c0 = cb * 16;
            __syncthreads();
            // stage weights: [cc][slot], coalesced from (k,c,slot) layout
#pragma unroll
            for (int r = 0; r < 2; r++) {
                int idx = tid + r * 256;
                int cc = idx >> 5, oc = idx & 31;
                wsm[cc][oc] = g_owt[(k * CIN + c0 + cc) * 32 + oc];
            }
            // stage im2col values: [cc][pp]
#pragma unroll
            for (int r = 0; r < 4; r++) {
                int idx = tid + r * 256;
                int cc = idx >> 6, pl = idx & 63;
                int p  = p0 + pl;
                int ho = p / WWW, wo = p % WWW;
                int y = ho - 1 + ky, x = wo - 1 + kx;
                float v = 0.f;
                if ((unsigned)y < (unsigned)HH && (unsigned)x < (unsigned)WWW)
                    v = x2[((b * CIN + c0 + cc) * HH + y) * WWW + x];
                vsm[cc][pl] = v;
            }
            __syncthreads();
#pragma unroll
            for (int cc = 0; cc < 16; cc++) {
                float2 w = *(const float2*)&wsm[cc][ty * 2];
                float4 v = *(const float4*)&vsm[cc][tx * 4];
                acc[0][0] = fmaf(w.x, v.x, acc[0][0]);
                acc[0][1] = fmaf(w.x, v.y, acc[0][1]);
                acc[0][2] = fmaf(w.x, v.z, acc[0][2]);
                acc[0][3] = fmaf(w.x, v.w, acc[0][3]);
                acc[1][0] = fmaf(w.y, v.x, acc[1][0]);
                acc[1][1] = fmaf(w.y, v.y, acc[1][1]);
                acc[1][2] = fmaf(w.y, v.z, acc[1][2]);
                acc[1][3] = fmaf(w.y, v.w, acc[1][3]);
            }
        }
    }

    // epilogue: bias; sigmoid for mask channels
#pragma unroll
    for (int i = 0; i < 2; i++) {
        int oc = ty * 2 + i;
#pragma unroll
        for (int j = 0; j < 4; j++) {
            int p = p0 + tx * 4 + j;
            if (oc < 18) {
                g_off[(b * 18 + oc) * PP + p] = acc[i][j] + offset_b[oc];
            } else if (oc < 27) {
                float s = acc[i][j] + mask_b[oc - 18];
                g_mask[(b * 9 + (oc - 18)) * PP + p] = 1.f / (1.f + expf(-s));
            }
        }
    }
}

// ---------------------------------------------------------------------------
// Kernel 2: modulated deformable conv v2 as implicit GEMM:
//   out[128o, 64p] = W[128, 1152] @ V[1152, 64]
// V generated on the fly by bilinear gather with precomputed corner metadata.
// Block: 256 threads, thread tile 8oc x 4p. Weights staged coalesced from g_wt.
// ---------------------------------------------------------------------------
__global__ __launch_bounds__(256) void deform_kernel(
    const float* __restrict__ x,
    const float* __restrict__ deform_b,
    float* __restrict__ out)
{
    __shared__ __align__(16) int   sidx[9][64][4];
    __shared__ __align__(16) float swt [9][64][4];
    __shared__ __align__(16) float wsm[16][128];
    __shared__ __align__(16) float vsm[16][64];

    const int tid = threadIdx.x;
    const int b  = blockIdx.y;
    const int p0 = blockIdx.x * PT;
    const int tx = tid & 15;        // -> 4 pixels
    const int ty = tid >> 4;        // -> 8 out channels

    // ---- precompute bilinear corner metadata for 64 pixels x 9 taps ----
    for (int idx = tid; idx < 9 * 64; idx += 256) {
        int k = idx >> 6, pl = idx & 63;
        int p  = p0 + pl;
        int ho = p / WWW, wo = p % WWW;
        int ky = k / 3, kx = k % 3;
        float dy = g_off[(b * 18 + 2 * k    ) * PP + p];
        float dx = g_off[(b * 18 + 2 * k + 1) * PP + p];
        float m  = g_mask[(b * 9 + k) * PP + p];
        float py = (float)(ho - 1 + ky) + dy;
        float px = (float)(wo - 1 + kx) + dx;
        float fy = floorf(py), fx = floorf(px);
        int y0 = (int)fy, x0 = (int)fx;
        int y1 = y0 + 1,  x1 = x0 + 1;
        float ly = py - fy, lx = px - fx;
        float hy = 1.f - ly, hx = 1.f - lx;
        bool vy0 = (unsigned)y0 < (unsigned)HH, vy1 = (unsigned)y1 < (unsigned)HH;
        bool vx0 = (unsigned)x0 < (unsigned)WWW, vx1 = (unsigned)x1 < (unsigned)WWW;
        bool v00 = vy0 && vx0, v01 = vy0 && vx1, v10 = vy1 && vx0, v11 = vy1 && vx1;
        sidx[k][pl][0] = v00 ? (y0 * WWW + x0) : 0;
        sidx[k][pl][1] = v01 ? (y0 * WWW + x1) : 0;
        sidx[k][pl][2] = v10 ? (y1 * WWW + x0) : 0;
        sidx[k][pl][3] = v11 ? (y1 * WWW + x1) : 0;
        swt[k][pl][0] = v00 ? hy * hx * m : 0.f;
        swt[k][pl][1] = v01 ? hy * lx * m : 0.f;
        swt[k][pl][2] = v10 ? ly * hx * m : 0.f;
        swt[k][pl][3] = v11 ? ly * lx * m : 0.f;
    }
    __syncthreads();

    float acc[8][4];
#pragma unroll
    for (int i = 0; i < 8; i++)
#pragma unroll
        for (int j = 0; j < 4; j++) acc[i][j] = 0.f;

    for (int k = 0; k < 9; k++) {
        for (int cb = 0; cb < 8; cb++) {
            const int c0 = cb * 16;
            __syncthreads();
            // stage weights: [cc][oc], coalesced float4 from (k,c,o) layout
#pragma unroll
            for (int r = 0; r < 2; r++) {
                int idx = tid + r * 256;           // 512 float4 total
                int cc = idx >> 5, oc4 = idx & 31;
                *(float4*)&wsm[cc][oc4 * 4] =
                    *(const float4*)&g_wt[(k * CIN + c0 + cc) * OO + oc4 * 4];
            }
            // stage sampled values: [cc][pp]
#pragma unroll
            for (int r = 0; r < 4; r++) {
                int idx = tid + r * 256;
                int cc = idx >> 6, pl = idx & 63;
                const float* base = x + (size_t)(b * CIN + c0 + cc) * PP;
                int4   id = *(const int4*)  &sidx[k][pl][0];
                float4 w  = *(const float4*)&swt [k][pl][0];
                float v = w.x * base[id.x];
                v = fmaf(w.y, base[id.y], v);
                v = fmaf(w.z, base[id.z], v);
                v = fmaf(w.w, base[id.w], v);
                vsm[cc][pl] = v;
            }
            __syncthreads();
            // 16-step rank-1 updates: 8oc x 4p per thread
#pragma unroll
            for (int cc = 0; cc < 16; cc++) {
                float4 wa = *(const float4*)&wsm[cc][ty * 8];
                float4 wb = *(const float4*)&wsm[cc][ty * 8 + 4];
                float4 v  = *(const float4*)&vsm[cc][tx * 4];
                float wv[8] = {wa.x, wa.y, wa.z, wa.w, wb.x, wb.y, wb.z, wb.w};
                float vv[4] = {v.x, v.y, v.z, v.w};
#pragma unroll
                for (int i = 0; i < 8; i++)
#pragma unroll
                    for (int j = 0; j < 4; j++)
                        acc[i][j] = fmaf(wv[i], vv[j], acc[i][j]);
            }
        }
    }

    // epilogue: bias + vectorized store
#pragma unroll
    for (int i = 0; i < 8; i++) {
        int oc = ty * 8 + i;
        float bias = deform_b[oc];
        float4 o;
        o.x = acc[i][0] + bias;
        o.y = acc[i][1] + bias;
        o.z = acc[i][2] + bias;
        o.w = acc[i][3] + bias;
        *(float4*)&out[(size_t)(b * OO + oc) * PP + p0 + tx * 4] = o;
    }
}

// ---------------------------------------------------------------------------
extern "C" void kernel_launch(void* const* d_in, const int* in_sizes, int n_in,
                              void* d_out, int out_size)
{
    const float* x        = (const float*)d_in[0];
    const float* x2       = (const float*)d_in[1];
    const float* offset_w = (const float*)d_in[2];
    const float* offset_b = (const float*)d_in[3];
    const float* mask_w   = (const float*)d_in[4];
    const float* mask_b   = (const float*)d_in[5];
    const float* deform_w = (const float*)d_in[6];
    const float* deform_b = (const float*)d_in[7];
    float* out = (float*)d_out;

    transpose_w_kernel<<<(9 * CIN * OO + 255) / 256, 256>>>(deform_w, offset_w, mask_w);
    dim3 grid(NPT, BB);
    offmask_kernel<<<grid, 256>>>(x2, offset_b, mask_b);
    deform_kernel<<<grid, 256>>>(x, deform_b, out);
}

// round 3
// speedup vs baseline: 2.0708x; 1.0754x over previous
#include <cuda_runtime.h>
#include <math.h>

// Problem constants
#define BB   4
#define CIN  128
#define HH   96
#define WWW  96
#define OO   128
#define PP   9216      // H*W
#define PT   64        // pixel tile per block
#define NPT  144       // PP / PT

// Scratch (device globals — no allocation allowed)
__device__ float g_off [BB * 18 * PP];        // (b, 2k+d, p)
__device__ float g_mask[BB * 9  * PP];        // (b, k, p) — sigmoid applied
__device__ float g_wt  [9 * CIN * OO];        // (k, c, o)  transposed deform_w
__device__ float g_owt [9 * CIN * 32];        // (k, c, slot) transposed offset/mask w

// ---- packed fp32x2 helpers (Blackwell FFMA2) --------------------------------
__device__ __forceinline__ void fma2(unsigned long long& d,
                                     unsigned long long a,
                                     unsigned long long b) {
    asm("fma.rn.f32x2 %0, %1, %2, %0;" : "+l"(d) : "l"(a), "l"(b));
}
__device__ __forceinline__ unsigned long long dup2(float w) {
    unsigned long long r;
    asm("mov.b64 %0, {%1, %1};" : "=l"(r) : "r"(__float_as_uint(w)));
    return r;
}
__device__ __forceinline__ float2 unpack2(unsigned long long v) {
    unsigned lo, hi;
    asm("mov.b64 {%0, %1}, %2;" : "=r"(lo), "=r"(hi) : "l"(v));
    return make_float2(__uint_as_float(lo), __uint_as_float(hi));
}

// ---------------------------------------------------------------------------
// Kernel 0: one-time weight transposes so GEMM staging is coalesced.
// ---------------------------------------------------------------------------
__global__ __launch_bounds__(256) void transpose_w_kernel(
    const float* __restrict__ dw,
    const float* __restrict__ ow,
    const float* __restrict__ mw)
{
    int i = blockIdx.x * 256 + threadIdx.x;
    if (i < 9 * CIN * OO) {
        int o = i & 127, c = (i >> 7) & 127, k = i >> 14;
        g_wt[i] = dw[(o * CIN + c) * 9 + k];
    }
    if (i < 9 * CIN * 32) {
        int s = i & 31, c = (i >> 5) & 127, k = i >> 12;
        float w = 0.f;
        if (s < 18)      w = ow[(s * CIN + c) * 9 + k];
        else if (s < 27) w = mw[((s - 18) * CIN + c) * 9 + k];
        g_owt[i] = w;
    }
}

// ---------------------------------------------------------------------------
// Kernel 1: offset conv (18ch) + mask conv (9ch, sigmoid), fused implicit GEMM
//   Y[32slots, 64p] = W[32,1152] @ Im2col[1152,64]
// Block: 256 threads, thread tile 2oc x 4p (2 f32x2 pairs).
// ---------------------------------------------------------------------------
__global__ __launch_bounds__(256) void offmask_kernel(
    const float* __restrict__ x2,
    const float* __restrict__ offset_b, const float* __restrict__ mask_b)
{
    __shared__ __align__(16) float wsm[16][32];
    __shared__ __align__(16) float vsm[16][64];

    const int tid = threadIdx.x;
    const int b  = blockIdx.y;
    const int p0 = blockIdx.x * PT;
    const int tx = tid & 15;        // -> 4 pixels
    const int ty = tid >> 4;        // -> 2 out channels

    unsigned long long acc2[2][2];
#pragma unroll
    for (int i = 0; i < 2; i++)
#pragma unroll
        for (int j = 0; j < 2; j++) acc2[i][j] = 0ull;

    for (int k = 0; k < 9; k++) {
        const int ky = k / 3, kx = k % 3;
        for (int cb = 0; cb < 8; cb++) {
            const int c0 = cb * 16;
            __syncthreads();
#pragma unroll
            for (int r = 0; r < 2; r++) {
                int idx = tid + r * 256;
                int cc = idx >> 5, oc = idx & 31;
                wsm[cc][oc] = g_owt[(k * CIN + c0 + cc) * 32 + oc];
            }
#pragma unroll
            for (int r = 0; r < 4; r++) {
                int idx = tid + r * 256;
                int cc = idx >> 6, pl = idx & 63;
                int p  = p0 + pl;
                int ho = p / WWW, wo = p % WWW;
                int y = ho - 1 + ky, x = wo - 1 + kx;
                float v = 0.f;
                if ((unsigned)y < (unsigned)HH && (unsigned)x < (unsigned)WWW)
                    v = x2[((b * CIN + c0 + cc) * HH + y) * WWW + x];
                vsm[cc][pl] = v;
            }
            __syncthreads();
#pragma unroll
            for (int cc = 0; cc < 16; cc++) {
                float2 w = *(const float2*)&wsm[cc][ty * 2];
                ulonglong2 v = *(const ulonglong2*)&vsm[cc][tx * 4];
                unsigned long long w0 = dup2(w.x), w1 = dup2(w.y);
                fma2(acc2[0][0], w0, v.x);
                fma2(acc2[0][1], w0, v.y);
                fma2(acc2[1][0], w1, v.x);
                fma2(acc2[1][1], w1, v.y);
            }
        }
    }

    // epilogue: bias; sigmoid for mask channels
#pragma unroll
    for (int i = 0; i < 2; i++) {
        int oc = ty * 2 + i;
        float a[4];
        float2 lo = unpack2(acc2[i][0]);
        float2 hi = unpack2(acc2[i][1]);
        a[0] = lo.x; a[1] = lo.y; a[2] = hi.x; a[3] = hi.y;
#pragma unroll
        for (int j = 0; j < 4; j++) {
            int p = p0 + tx * 4 + j;
            if (oc < 18) {
                g_off[(b * 18 + oc) * PP + p] = a[j] + offset_b[oc];
            } else if (oc < 27) {
                float s = a[j] + mask_b[oc - 18];
                g_mask[(b * 9 + (oc - 18)) * PP + p] = 1.f / (1.f + expf(-s));
            }
        }
    }
}

// ---------------------------------------------------------------------------
// Kernel 2: modulated deformable conv v2 as implicit GEMM:
//   out[128o, 64p] = W[128, 1152] @ V[1152, 64]
// V generated on the fly by bilinear gather with precomputed corner metadata.
// Block: 256 threads, thread tile 8oc x 4p (2 f32x2 pairs per oc).
// ---------------------------------------------------------------------------
__global__ __launch_bounds__(256) void deform_kernel(
    const float* __restrict__ x,
    const float* __restrict__ deform_b,
    float* __restrict__ out)
{
    __shared__ __align__(16) int   sidx[9][64][4];
    __shared__ __align__(16) float swt [9][64][4];
    __shared__ __align__(16) float wsm[16][128];
    __shared__ __align__(16) float vsm[16][64];

    const int tid = threadIdx.x;
    const int b  = blockIdx.y;
    const int p0 = blockIdx.x * PT;
    const int tx = tid & 15;        // -> 4 pixels
    const int ty = tid >> 4;        // -> 8 out channels

    // ---- precompute bilinear corner metadata for 64 pixels x 9 taps ----
    for (int idx = tid; idx < 9 * 64; idx += 256) {
        int k = idx >> 6, pl = idx & 63;
        int p  = p0 + pl;
        int ho = p / WWW, wo = p % WWW;
        int ky = k / 3, kx = k % 3;
        float dy = g_off[(b * 18 + 2 * k    ) * PP + p];
        float dx = g_off[(b * 18 + 2 * k + 1) * PP + p];
        float m  = g_mask[(b * 9 + k) * PP + p];
        float py = (float)(ho - 1 + ky) + dy;
        float px = (float)(wo - 1 + kx) + dx;
        float fy = floorf(py), fx = floorf(px);
        int y0 = (int)fy, x0 = (int)fx;
        int y1 = y0 + 1,  x1 = x0 + 1;
        float ly = py - fy, lx = px - fx;
        float hy = 1.f - ly, hx = 1.f - lx;
        bool vy0 = (unsigned)y0 < (unsigned)HH, vy1 = (unsigned)y1 < (unsigned)HH;
        bool vx0 = (unsigned)x0 < (unsigned)WWW, vx1 = (unsigned)x1 < (unsigned)WWW;
        bool v00 = vy0 && vx0, v01 = vy0 && vx1, v10 = vy1 && vx0, v11 = vy1 && vx1;
        sidx[k][pl][0] = v00 ? (y0 * WWW + x0) : 0;
        sidx[k][pl][1] = v01 ? (y0 * WWW + x1) : 0;
        sidx[k][pl][2] = v10 ? (y1 * WWW + x0) : 0;
        sidx[k][pl][3] = v11 ? (y1 * WWW + x1) : 0;
        swt[k][pl][0] = v00 ? hy * hx * m : 0.f;
        swt[k][pl][1] = v01 ? hy * lx * m : 0.f;
        swt[k][pl][2] = v10 ? ly * hx * m : 0.f;
        swt[k][pl][3] = v11 ? ly * lx * m : 0.f;
    }
    __syncthreads();

    unsigned long long acc2[8][2];
#pragma unroll
    for (int i = 0; i < 8; i++)
#pragma unroll
        for (int j = 0; j < 2; j++) acc2[i][j] = 0ull;

    for (int k = 0; k < 9; k++) {
        for (int cb = 0; cb < 8; cb++) {
            const int c0 = cb * 16;
            __syncthreads();
            // stage weights: [cc][oc], coalesced float4 from (k,c,o) layout
#pragma unroll
            for (int r = 0; r < 2; r++) {
                int idx = tid + r * 256;           // 512 float4 total
                int cc = idx >> 5, oc4 = idx & 31;
                *(float4*)&wsm[cc][oc4 * 4] =
                    *(const float4*)&g_wt[(k * CIN + c0 + cc) * OO + oc4 * 4];
            }
            // stage sampled values: [cc][pp]
#pragma unroll
            for (int r = 0; r < 4; r++) {
                int idx = tid + r * 256;
                int cc = idx >> 6, pl = idx & 63;
                const float* base = x + (size_t)(b * CIN + c0 + cc) * PP;
                int4   id = *(const int4*)  &sidx[k][pl][0];
                float4 w  = *(const float4*)&swt [k][pl][0];
                float v = w.x * base[id.x];
                v = fmaf(w.y, base[id.y], v);
                v = fmaf(w.z, base[id.z], v);
                v = fmaf(w.w, base[id.w], v);
                vsm[cc][pl] = v;
            }
            __syncthreads();
            // 16-step rank-1 updates: 8oc x 4p per thread, packed f32x2
#pragma unroll
            for (int cc = 0; cc < 16; cc++) {
                float4 wa = *(const float4*)&wsm[cc][ty * 8];
                float4 wb = *(const float4*)&wsm[cc][ty * 8 + 4];
                ulonglong2 v = *(const ulonglong2*)&vsm[cc][tx * 4];
                float wv[8] = {wa.x, wa.y, wa.z, wa.w, wb.x, wb.y, wb.z, wb.w};
#pragma unroll
                for (int i = 0; i < 8; i++) {
                    unsigned long long wp = dup2(wv[i]);
                    fma2(acc2[i][0], wp, v.x);
                    fma2(acc2[i][1], wp, v.y);
                }
            }
        }
    }

    // epilogue: bias + vectorized store
#pragma unroll
    for (int i = 0; i < 8; i++) {
        int oc = ty * 8 + i;
        float bias = deform_b[oc];
        float2 lo = unpack2(acc2[i][0]);
        float2 hi = unpack2(acc2[i][1]);
        float4 o;
        o.x = lo.x + bias;
        o.y = lo.y + bias;
        o.z = hi.x + bias;
        o.w = hi.y + bias;
        *(float4*)&out[(size_t)(b * OO + oc) * PP + p0 + tx * 4] = o;
    }
}

// ---------------------------------------------------------------------------
extern "C" void kernel_launch(void* const* d_in, const int* in_sizes, int n_in,
                              void* d_out, int out_size)
{
    const float* x        = (const float*)d_in[0];
    const float* x2       = (const float*)d_in[1];
    const float* offset_w = (const float*)d_in[2];
    const float* offset_b = (const float*)d_in[3];
    const float* mask_w   = (const float*)d_in[4];
    const float* mask_b   = (const float*)d_in[5];
    const float* deform_w = (const float*)d_in[6];
    const float* deform_b = (const float*)d_in[7];
    float* out = (float*)d_out;

    transpose_w_kernel<<<(9 * CIN * OO + 255) / 256, 256>>>(deform_w, offset_w, mask_w);
    dim3 grid(NPT, BB);
    offmask_kernel<<<grid, 256>>>(x2, offset_b, mask_b);
    deform_kernel<<<grid, 256>>>(x, deform_b, out);
}